// round 8
// baseline (speedup 1.0000x reference)
#include <cuda_runtime.h>

// out[r][c] = posenc(X[r]) . W[3*voxel_ids[p] + c],  r = row_ids[p]
//
//  K1 rank:    pos[p] = atomicAdd(cnt[voxel_ids[p]], 1)   (counters 128B-strided)
//  K2 scan:    binstart = exclusive_scan(cnt); cnt = 0 (self-reset for graph replay)
//  K3 scatter: g_pts[binstart[v]+pos[p]] = float4(x0,x1,x2,bits(row_ids[p]))
//  K4 main:    CTA per voxel; weights packed (sin,cos) as float2 in smem;
//              sincos fused directly into accumulators -> ~32 regs (was 242).

#define NUM_VOXELS 512
#define NPTS_MAX (1 << 18)
#define PAD 32                    // counter stride in ints = 128 B

__device__ int    g_cnt[NUM_VOXELS * PAD];   // zero-init; self-reset by K2
__device__ int    g_pos[NPTS_MAX];
__device__ int    g_binstart[NUM_VOXELS + 1];
__device__ float4 g_pts[NPTS_MAX];

// ---- K1: per-point rank within its voxel ----
__global__ void __launch_bounds__(256)
rank_kernel(const int* __restrict__ voxel_ids, int n)
{
    int p = blockIdx.x * 256 + threadIdx.x;
    if (p >= n) return;
    g_pos[p] = atomicAdd(&g_cnt[voxel_ids[p] * PAD], 1);
}

// ---- K2: scan 512 counts -> binstart, zero counters ----
__global__ void __launch_bounds__(NUM_VOXELS)
scan_kernel(int n)
{
    __shared__ int sh[NUM_VOXELS];
    const int t = threadIdx.x;
    const int val = g_cnt[t * PAD];
    g_cnt[t * PAD] = 0;                  // reset for next graph replay
    sh[t] = val;
    __syncthreads();
#pragma unroll
    for (int off = 1; off < NUM_VOXELS; off <<= 1) {
        int x = sh[t];
        if (t >= off) x += sh[t - off];
        __syncthreads();
        sh[t] = x;
        __syncthreads();
    }
    g_binstart[t] = sh[t] - val;         // exclusive
    if (t == NUM_VOXELS - 1) g_binstart[NUM_VOXELS] = n;
}

// ---- K3: scatter payload into voxel-sorted order ----
__global__ void __launch_bounds__(256)
scatter_kernel(const float* __restrict__ X,
               const int* __restrict__ row_ids,
               const int* __restrict__ voxel_ids,
               int n)
{
    int p = blockIdx.x * 256 + threadIdx.x;
    if (p >= n) return;
    const int v = voxel_ids[p];
    const int dst = g_binstart[v] + g_pos[p];
    const int r = row_ids[p];
    float4 pay;
    pay.x = X[3 * r + 0];
    pay.y = X[3 * r + 1];
    pay.z = X[3 * r + 2];
    pay.w = __int_as_float(r);
    g_pts[dst] = pay;
}

// ---- K4: main — CTA per voxel, fused sincos->FMA, float2-packed weights ----
// smem layout: Wp[c][a] = {w_sin, w_cos} for angle a = 3f+d  (a in 0..29),
// plus raw[c][d] weights. Broadcast LDS.64, no big register arrays.
__global__ void __launch_bounds__(256)
voxel_main_kernel(const float* __restrict__ W,
                  float* __restrict__ out)
{
    __shared__ float2 Wp[3][32];     // 30 angles + pad
    __shared__ float  Wraw[3][4];    // raw x weights + pad
    const int v = blockIdx.x;
    const int t = threadIdx.x;

    if (t < 90) {
        const int c = t / 30, a = t - 30 * c;
        const int f = a / 3, d = a - 3 * f;
        const float* row = W + (3 * v + c) * 63;
        Wp[c][a] = make_float2(row[3 + 6 * f + d], row[3 + 6 * f + 3 + d]);
    } else if (t < 99) {
        const int u = t - 90;
        const int c = u / 3, d = u - 3 * c;
        Wraw[c][d] = W[(3 * v + c) * 63 + d];
    }
    __syncthreads();

    const int start = g_binstart[v];
    const int cnt   = g_binstart[v + 1] - start;

    for (int i = t; i < cnt; i += 256) {
        const float4 pay = g_pts[start + i];
        const float x0 = pay.x, x1 = pay.y, x2 = pay.z;
        const int   r  = __float_as_int(pay.w);

        float a0 = x0 * Wraw[0][0];
        a0 = fmaf(x1, Wraw[0][1], a0); a0 = fmaf(x2, Wraw[0][2], a0);
        float a1 = x0 * Wraw[1][0];
        a1 = fmaf(x1, Wraw[1][1], a1); a1 = fmaf(x2, Wraw[1][2], a1);
        float a2 = x0 * Wraw[2][0];
        a2 = fmaf(x1, Wraw[2][1], a2); a2 = fmaf(x2, Wraw[2][2], a2);

#pragma unroll
        for (int f = 0; f < 10; ++f) {
            const float sc = (float)(1 << f);
#pragma unroll
            for (int d = 0; d < 3; ++d) {
                const float xv = (d == 0) ? x0 : ((d == 1) ? x1 : x2);
                float s, c;
                __sincosf(xv * sc, &s, &c);
                const int a = 3 * f + d;
                const float2 w0 = Wp[0][a];
                a0 = fmaf(s, w0.x, a0); a0 = fmaf(c, w0.y, a0);
                const float2 w1 = Wp[1][a];
                a1 = fmaf(s, w1.x, a1); a1 = fmaf(c, w1.y, a1);
                const float2 w2 = Wp[2][a];
                a2 = fmaf(s, w2.x, a2); a2 = fmaf(c, w2.y, a2);
            }
        }

        out[3 * r + 0] = a0;
        out[3 * r + 1] = a1;
        out[3 * r + 2] = a2;
    }
}

extern "C" void kernel_launch(void* const* d_in, const int* in_sizes, int n_in,
                              void* d_out, int out_size)
{
    const float* X         = (const float*)d_in[0];
    const float* W         = (const float*)d_in[1];
    const int*   row_ids   = (const int*)d_in[2];
    const int*   voxel_ids = (const int*)d_in[3];
    float*       out       = (float*)d_out;

    const int n = in_sizes[0] / 3;               // N_POINTS
    const int nb = (n + 255) / 256;

    rank_kernel<<<nb, 256>>>(voxel_ids, n);
    scan_kernel<<<1, NUM_VOXELS>>>(n);
    scatter_kernel<<<nb, 256>>>(X, row_ids, voxel_ids, n);
    voxel_main_kernel<<<NUM_VOXELS, 256>>>(W, out);
}

// round 9
// speedup vs baseline: 1.3380x; 1.3380x over previous
#include <cuda_runtime.h>

// out[r][c] = posenc(X[r]) . W[3*voxel_ids[p] + c],  r = row_ids[p]
//
//  K1 rank:    pos[p] = atomicAdd(cnt[voxel_ids[p]], 1)   (counters 128B-strided)
//  K2 scan:    binstart = exclusive_scan(cnt); cnt = 0 (self-reset for graph replay)
//  K3 scatter: g_pts[binstart[v]+pos[p]] = float4(x0,x1,x2,bits(row_ids[p]))
//  K4 main:    2 CTAs per voxel; weights packed (sin,cos) float2 in smem;
//              sincos fused into accumulators; __launch_bounds__(256,6) caps
//              regs at 42 (R8 showed ptxas ballooning to 240 without a cap).

#define NUM_VOXELS 512
#define NPTS_MAX (1 << 18)
#define PAD 32                    // counter stride in ints = 128 B

__device__ int    g_cnt[NUM_VOXELS * PAD];   // zero-init; self-reset by K2
__device__ int    g_pos[NPTS_MAX];
__device__ int    g_binstart[NUM_VOXELS + 1];
__device__ float4 g_pts[NPTS_MAX];

// ---- K1: per-point rank within its voxel ----
__global__ void __launch_bounds__(256)
rank_kernel(const int* __restrict__ voxel_ids, int n)
{
    int p = blockIdx.x * 256 + threadIdx.x;
    if (p >= n) return;
    g_pos[p] = atomicAdd(&g_cnt[voxel_ids[p] * PAD], 1);
}

// ---- K2: scan 512 counts -> binstart, zero counters ----
__global__ void __launch_bounds__(NUM_VOXELS)
scan_kernel(int n)
{
    __shared__ int sh[NUM_VOXELS];
    const int t = threadIdx.x;
    const int val = g_cnt[t * PAD];
    g_cnt[t * PAD] = 0;                  // reset for next graph replay
    sh[t] = val;
    __syncthreads();
#pragma unroll
    for (int off = 1; off < NUM_VOXELS; off <<= 1) {
        int x = sh[t];
        if (t >= off) x += sh[t - off];
        __syncthreads();
        sh[t] = x;
        __syncthreads();
    }
    g_binstart[t] = sh[t] - val;         // exclusive
    if (t == NUM_VOXELS - 1) g_binstart[NUM_VOXELS] = n;
}

// ---- K3: scatter payload into voxel-sorted order ----
__global__ void __launch_bounds__(256)
scatter_kernel(const float* __restrict__ X,
               const int* __restrict__ row_ids,
               const int* __restrict__ voxel_ids,
               int n)
{
    int p = blockIdx.x * 256 + threadIdx.x;
    if (p >= n) return;
    const int v = voxel_ids[p];
    const int dst = g_binstart[v] + g_pos[p];
    const int r = row_ids[p];
    float4 pay;
    pay.x = X[3 * r + 0];
    pay.y = X[3 * r + 1];
    pay.z = X[3 * r + 2];
    pay.w = __int_as_float(r);
    g_pts[dst] = pay;
}

// ---- K4: main — 2 CTAs per voxel, fused sincos->FMA, reg-capped ----
__global__ void __launch_bounds__(256, 6)
voxel_main_kernel(const float* __restrict__ W,
                  float* __restrict__ out)
{
    __shared__ float2 Wp[3][32];     // (sin,cos) weight pairs per angle a=3f+d
    __shared__ float  Wraw[3][4];    // raw x weights
    const int v    = blockIdx.x >> 1;
    const int half = blockIdx.x & 1;
    const int t = threadIdx.x;

    if (t < 90) {
        const int c = t / 30, a = t - 30 * c;
        const int f = a / 3, d = a - 3 * f;
        const float* row = W + (3 * v + c) * 63;
        Wp[c][a] = make_float2(row[3 + 6 * f + d], row[3 + 6 * f + 3 + d]);
    } else if (t < 99) {
        const int u = t - 90;
        const int c = u / 3, d = u - 3 * c;
        Wraw[c][d] = W[(3 * v + c) * 63 + d];
    }
    __syncthreads();

    const int start = g_binstart[v];
    const int cnt   = g_binstart[v + 1] - start;

    for (int i = half * 256 + t; i < cnt; i += 512) {
        const float4 pay = g_pts[start + i];
        const float x0 = pay.x, x1 = pay.y, x2 = pay.z;
        const int   r  = __float_as_int(pay.w);

        float a0 = x0 * Wraw[0][0];
        a0 = fmaf(x1, Wraw[0][1], a0); a0 = fmaf(x2, Wraw[0][2], a0);
        float a1 = x0 * Wraw[1][0];
        a1 = fmaf(x1, Wraw[1][1], a1); a1 = fmaf(x2, Wraw[1][2], a1);
        float a2 = x0 * Wraw[2][0];
        a2 = fmaf(x1, Wraw[2][1], a2); a2 = fmaf(x2, Wraw[2][2], a2);

#pragma unroll 2
        for (int f = 0; f < 10; ++f) {
            const float sc = (float)(1 << f);
#pragma unroll
            for (int d = 0; d < 3; ++d) {
                const float xv = (d == 0) ? x0 : ((d == 1) ? x1 : x2);
                float s, c;
                __sincosf(xv * sc, &s, &c);
                const int a = 3 * f + d;
                const float2 w0 = Wp[0][a];
                a0 = fmaf(s, w0.x, a0); a0 = fmaf(c, w0.y, a0);
                const float2 w1 = Wp[1][a];
                a1 = fmaf(s, w1.x, a1); a1 = fmaf(c, w1.y, a1);
                const float2 w2 = Wp[2][a];
                a2 = fmaf(s, w2.x, a2); a2 = fmaf(c, w2.y, a2);
            }
        }

        out[3 * r + 0] = a0;
        out[3 * r + 1] = a1;
        out[3 * r + 2] = a2;
    }
}

extern "C" void kernel_launch(void* const* d_in, const int* in_sizes, int n_in,
                              void* d_out, int out_size)
{
    const float* X         = (const float*)d_in[0];
    const float* W         = (const float*)d_in[1];
    const int*   row_ids   = (const int*)d_in[2];
    const int*   voxel_ids = (const int*)d_in[3];
    float*       out       = (float*)d_out;

    const int n = in_sizes[0] / 3;               // N_POINTS
    const int nb = (n + 255) / 256;

    rank_kernel<<<nb, 256>>>(voxel_ids, n);
    scan_kernel<<<1, NUM_VOXELS>>>(n);
    scatter_kernel<<<nb, 256>>>(X, row_ids, voxel_ids, n);
    voxel_main_kernel<<<NUM_VOXELS * 2, 256>>>(W, out);
}